// round 5
// baseline (speedup 1.0000x reference)
#include <cuda_runtime.h>

#define N_NODES 100000
#define IN_DIM 512
#define HIDDEN 16
#define OUT_DIM 64

// ---------------- device scratch (no allocations allowed) ----------------
__device__ __align__(16) float g_z[(size_t)N_NODES * HIDDEN];   // x@W1, pre-scaled by dinv[src]
__device__ __align__(16) float g_h[(size_t)N_NODES * HIDDEN];   // agg1 -> h1 (pre-scaled)
__device__ __align__(16) float g_a2[(size_t)N_NODES * HIDDEN];  // agg2
__device__ float g_deg[N_NODES];
__device__ float g_dinv[N_NODES];

// ---------------- helpers ----------------
__device__ __forceinline__ unsigned long long fma2(unsigned long long a,
                                                   unsigned long long b,
                                                   unsigned long long c) {
    unsigned long long d;
    asm("fma.rn.f32x2 %0, %1, %2, %3;" : "=l"(d) : "l"(a), "l"(b), "l"(c));
    return d;
}
__device__ __forceinline__ unsigned long long add2(unsigned long long a,
                                                   unsigned long long b) {
    unsigned long long d;
    asm("add.rn.f32x2 %0, %1, %2;" : "=l"(d) : "l"(a), "l"(b));
    return d;
}
__device__ __forceinline__ unsigned long long dup2(float v) {
    unsigned long long d;
    asm("mov.b64 %0, {%1, %2};" : "=l"(d) : "f"(v), "f"(v));
    return d;
}
__device__ __forceinline__ unsigned long long shfl_xor_u64(unsigned long long v, int m) {
    unsigned lo = (unsigned)v, hi = (unsigned)(v >> 32);
    lo = __shfl_xor_sync(0xffffffffu, lo, m);
    hi = __shfl_xor_sync(0xffffffffu, hi, m);
    return ((unsigned long long)hi << 32) | (unsigned long long)lo;
}
__device__ __forceinline__ void red_add_v4(float* p, float a, float b, float c, float d) {
    asm volatile("red.global.add.v4.f32 [%0], {%1, %2, %3, %4};"
                 :: "l"(p), "f"(a), "f"(b), "f"(c), "f"(d) : "memory");
}
__device__ __forceinline__ void red_add_f32(float* p, float v) {
    asm volatile("red.global.add.f32 [%0], %1;" :: "l"(p), "f"(v) : "memory");
}

// ---------------- kernels ----------------

// zero agg buffers, deg = 1 (self loop)
__global__ void k_init() {
    int t = blockIdx.x * blockDim.x + threadIdx.x;
    float4 z4 = make_float4(0.f, 0.f, 0.f, 0.f);
    if (t < N_NODES * 4) {
        ((float4*)g_h)[t] = z4;
        ((float4*)g_a2)[t] = z4;
    }
    if (t < N_NODES) g_deg[t] = 1.0f;
}

// 4 edges per thread; tail handled by one guarded thread
__global__ void k_deg(const int* __restrict__ dst, int E4, int E) {
    int t = blockIdx.x * blockDim.x + threadIdx.x;
    if (t < E4) {
        int4 d = __ldg((const int4*)dst + t);
        red_add_f32(&g_deg[d.x], 1.0f);
        red_add_f32(&g_deg[d.y], 1.0f);
        red_add_f32(&g_deg[d.z], 1.0f);
        red_add_f32(&g_deg[d.w], 1.0f);
    } else if (t == E4) {
        for (int e = E4 * 4; e < E; e++)
            red_add_f32(&g_deg[__ldg(dst + e)], 1.0f);
    }
}

__global__ void k_dinv() {
    int i = blockIdx.x * blockDim.x + threadIdx.x;
    if (i < N_NODES) g_dinv[i] = rsqrtf(g_deg[i]);
}

// z = (x @ W1) * dinv[row], warp-cooperative.
// Warp = 4 row-slots (rs) x 8 k-lanes (kl). Lane kl covers k = k0+4*kl+j, j=0..3.
// x loads: 8 lanes read 128B contiguous per row -> 4 lines per warp LDG.
// W1 in smem, bank-swizzled so the 8 k-lanes hit 8 distinct bank-quads:
//   float4 slot of (k, c) at index (k>>1)*8 + 4*((k&1)^((k>>4)&1)) + ((c+((k>>2)&3))&3)
// Row-slot groups read identical addresses (broadcast, no extra traffic).
__global__ __launch_bounds__(256) void k_gemm1(const float* __restrict__ x,
                                               const float* __restrict__ W1) {
    __shared__ __align__(16) float4 wq[IN_DIM * 4];  // 32 KB, swizzled
    {
        const float4* w4 = (const float4*)W1;
        for (int i = threadIdx.x; i < IN_DIM * 4; i += 256) {
            int k = i >> 2, c = i & 3;
            int q = 4 * ((k & 1) ^ ((k >> 4) & 1)) + ((c + ((k >> 2) & 3)) & 3);
            wq[(k >> 1) * 8 + q] = w4[i];
        }
    }
    __syncthreads();

    int lane = threadIdx.x & 31;
    int rs = lane >> 3;        // row slot 0..3
    int kl = lane & 7;         // k-lane 0..7
    int klh = kl >> 2;         // 0 or 1
    int t = kl & 3;
    // per-lane constant quad offsets for logical c = 0..3
    int o0 = t, o1 = (t + 1) & 3, o2 = (t + 2) & 3, o3 = (t + 3) & 3;
    int pa = 4 * klh;          // quad base for even j
    int pb = 4 - 4 * klh;      // quad base for odd j   (4*(1^klh))

    int warps_total = gridDim.x * 8;
    int wid = (blockIdx.x * 256 + threadIdx.x) >> 5;

    for (long long rb = (long long)wid * 4; rb < N_NODES; rb += (long long)warps_total * 4) {
        long long row = rb + rs;                     // N_NODES % 4 == 0 -> always valid
        const float4* xr = (const float4*)(x + row * IN_DIM);

        unsigned long long acc[8];
#pragma unroll
        for (int i = 0; i < 8; i++) acc[i] = 0ull;

#pragma unroll 1
        for (int ch = 0; ch < 16; ch += 4) {
            float4 xb[4];
#pragma unroll
            for (int u = 0; u < 4; u++) xb[u] = xr[(ch + u) * 8 + kl];
#pragma unroll
            for (int u = 0; u < 4; u++) {
                int base = (ch + u) * 128 + 16 * kl;   // 4*k0 + 16*kl, k0 = (ch+u)*32
                const float* f = (const float*)&xb[u];
#pragma unroll
                for (int j = 0; j < 4; j++) {
                    int idx = base + ((j >> 1) ? 8 : 0) + ((j & 1) ? pb : pa);
                    unsigned long long d = dup2(f[j]);
                    float4 w0 = wq[idx + o0];
                    float4 w1 = wq[idx + o1];
                    float4 w2 = wq[idx + o2];
                    float4 w3 = wq[idx + o3];
                    acc[0] = fma2(d, *(const unsigned long long*)&w0.x, acc[0]);
                    acc[1] = fma2(d, *(const unsigned long long*)&w0.z, acc[1]);
                    acc[2] = fma2(d, *(const unsigned long long*)&w1.x, acc[2]);
                    acc[3] = fma2(d, *(const unsigned long long*)&w1.z, acc[3]);
                    acc[4] = fma2(d, *(const unsigned long long*)&w2.x, acc[4]);
                    acc[5] = fma2(d, *(const unsigned long long*)&w2.z, acc[5]);
                    acc[6] = fma2(d, *(const unsigned long long*)&w3.x, acc[6]);
                    acc[7] = fma2(d, *(const unsigned long long*)&w3.z, acc[7]);
                }
            }
        }

        // reduce across the 8 k-lanes (butterfly); all lanes end with full sums
#pragma unroll
        for (int m = 1; m < 8; m <<= 1) {
#pragma unroll
            for (int c8 = 0; c8 < 8; c8++)
                acc[c8] = add2(acc[c8], shfl_xor_u64(acc[c8], m));
        }

        if (kl == 0) {
            float dv = g_dinv[row];
            float4* zo = (float4*)(g_z + row * HIDDEN);
#pragma unroll
            for (int i = 0; i < 4; i++) {
                float2 a = *(float2*)&acc[2 * i];
                float2 b = *(float2*)&acc[2 * i + 1];
                zo[i] = make_float4(a.x * dv, a.y * dv, b.x * dv, b.y * dv);
            }
        }
    }
}

// edge scatter: out[dst] += vals[src]   (vals pre-scaled by dinv[src];
// dinv[dst] folded into the following per-node pass). 4 edges/thread.
template <int LAYER>
__global__ __launch_bounds__(256) void k_scatter(const int* __restrict__ src,
                                                 const int* __restrict__ dst,
                                                 int E4, int E) {
    int t = blockIdx.x * blockDim.x + threadIdx.x;
    const float* vals = (LAYER == 0) ? g_z : g_h;
    float* out = (LAYER == 0) ? g_h : g_a2;

    if (t < E4) {
        int4 s = __ldg((const int4*)src + t);
        int4 d = __ldg((const int4*)dst + t);
        const int sv[4] = {s.x, s.y, s.z, s.w};
        const int dv[4] = {d.x, d.y, d.z, d.w};
        float4 v[4][4];
#pragma unroll
        for (int e = 0; e < 4; e++) {
            const float4* vp = (const float4*)(vals + (size_t)sv[e] * HIDDEN);
#pragma unroll
            for (int j = 0; j < 4; j++) v[e][j] = vp[j];
        }
#pragma unroll
        for (int e = 0; e < 4; e++) {
            float* o = out + (size_t)dv[e] * HIDDEN;
#pragma unroll
            for (int j = 0; j < 4; j++)
                red_add_v4(o + j * 4, v[e][j].x, v[e][j].y, v[e][j].z, v[e][j].w);
        }
    } else if (t == E4) {
        for (int e = E4 * 4; e < E; e++) {
            int s = __ldg(src + e);
            int d = __ldg(dst + e);
            const float4* vp = (const float4*)(vals + (size_t)s * HIDDEN);
            float* o = out + (size_t)d * HIDDEN;
#pragma unroll
            for (int j = 0; j < 4; j++) {
                float4 vv = vp[j];
                red_add_v4(o + j * 4, vv.x, vv.y, vv.z, vv.w);
            }
        }
    }
}

// h1 = relu((agg1 + z) * dinv + b1); store pre-scaled: g_h = h1 * dinv
__global__ void k_h1(const float* __restrict__ b1) {
    int t = blockIdx.x * blockDim.x + threadIdx.x;
    if (t >= N_NODES * 4) return;
    int i = t >> 2;
    int j = t & 3;
    float di = g_dinv[i];
    float4 a = ((const float4*)g_h)[t];
    float4 zz = ((const float4*)g_z)[t];
    float4 bb = __ldg((const float4*)b1 + j);
    float4 r;
    r.x = fmaxf(fmaf(a.x + zz.x, di, bb.x), 0.f) * di;
    r.y = fmaxf(fmaf(a.y + zz.y, di, bb.y), 0.f) * di;
    r.z = fmaxf(fmaf(a.z + zz.z, di, bb.z), 0.f) * di;
    r.w = fmaxf(fmaf(a.w + zz.w, di, bb.w), 0.f) * di;
    ((float4*)g_h)[t] = r;
}

// out = ((agg2 + h1s) * dinv) @ W2 + b2    (h1s = h1*dinv)
// 4 threads per row, each computes 16 output cols. W2 (4KB) in smem.
__global__ __launch_bounds__(256) void k_gemm2(const float* __restrict__ W2,
                                               const float* __restrict__ b2,
                                               float* __restrict__ out) {
    __shared__ __align__(16) float ws[HIDDEN * OUT_DIM];  // 1024 floats
    ((float4*)ws)[threadIdx.x] = ((const float4*)W2)[threadIdx.x];  // 256 float4
    __syncthreads();

    int gid = blockIdx.x * 256 + threadIdx.x;
    int r = gid >> 2;
    int cg = gid & 3;
    if (r >= N_NODES) return;

    float di = g_dinv[r];
    float hk[HIDDEN];
    const float4* A = (const float4*)(g_a2 + (size_t)r * HIDDEN);
    const float4* H = (const float4*)(g_h + (size_t)r * HIDDEN);
#pragma unroll
    for (int q = 0; q < 4; q++) {
        float4 a = A[q];
        float4 h = H[q];
        hk[4 * q + 0] = (a.x + h.x) * di;
        hk[4 * q + 1] = (a.y + h.y) * di;
        hk[4 * q + 2] = (a.z + h.z) * di;
        hk[4 * q + 3] = (a.w + h.w) * di;
    }

    float4 acc[4];
#pragma unroll
    for (int q = 0; q < 4; q++) acc[q] = make_float4(0.f, 0.f, 0.f, 0.f);

#pragma unroll
    for (int k = 0; k < HIDDEN; k++) {
        float xv = hk[k];
        const float4* wr = (const float4*)(ws + k * OUT_DIM + cg * 16);
#pragma unroll
        for (int q = 0; q < 4; q++) {
            float4 w = wr[q];
            acc[q].x = fmaf(xv, w.x, acc[q].x);
            acc[q].y = fmaf(xv, w.y, acc[q].y);
            acc[q].z = fmaf(xv, w.z, acc[q].z);
            acc[q].w = fmaf(xv, w.w, acc[q].w);
        }
    }

    const float4* bb = (const float4*)b2 + cg * 4;
    float4* O = (float4*)(out + (size_t)r * OUT_DIM) + cg * 4;
#pragma unroll
    for (int q = 0; q < 4; q++) {
        float4 b = __ldg(bb + q);
        O[q] = make_float4(acc[q].x + b.x, acc[q].y + b.y,
                           acc[q].z + b.z, acc[q].w + b.w);
    }
}

// ---------------- launch ----------------
extern "C" void kernel_launch(void* const* d_in, const int* in_sizes, int n_in,
                              void* d_out, int out_size) {
    const float* x = nullptr;
    const float* W1 = nullptr;
    const float* b1 = nullptr;
    const float* W2 = nullptr;
    const float* b2 = nullptr;
    const int* ei = nullptr;
    int E = 0;
    for (int i = 0; i < n_in; i++) {
        long long sz = in_sizes[i];
        if (sz == (long long)N_NODES * IN_DIM)      x  = (const float*)d_in[i];
        else if (sz == IN_DIM * HIDDEN)             W1 = (const float*)d_in[i];
        else if (sz == HIDDEN)                      b1 = (const float*)d_in[i];
        else if (sz == HIDDEN * OUT_DIM)            W2 = (const float*)d_in[i];
        else if (sz == OUT_DIM)                     b2 = (const float*)d_in[i];
        else { ei = (const int*)d_in[i]; E = (int)(sz / 2); }
    }
    const int* src = ei;
    const int* dst = ei + E;
    float* out = (float*)d_out;

    const int TB = 256;
    int E4 = E / 4;  // 4 edges/thread; tail in-kernel
    int grid_n4 = (N_NODES * 4 + TB - 1) / TB;
    int grid_n  = (N_NODES + TB - 1) / TB;
    int grid_e4 = (E4 + 1 + TB - 1) / TB;  // +1 slot for tail thread
    int grid_g1 = 592;                      // grid-stride over 25k warp row-groups

    k_init<<<grid_n4, TB>>>();
    k_deg<<<grid_e4, TB>>>(dst, E4, E);
    k_dinv<<<grid_n, TB>>>();
    k_gemm1<<<grid_g1, TB>>>(x, W1);
    k_scatter<0><<<grid_e4, TB>>>(src, dst, E4, E);
    k_h1<<<grid_n4, TB>>>(b1);
    k_scatter<1><<<grid_e4, TB>>>(src, dst, E4, E);
    k_gemm2<<<grid_n4, TB>>>(W2, b2, out);
}